// round 13
// baseline (speedup 1.0000x reference)
#include <cuda_runtime.h>
#include <cstdint>
#include <cstddef>

#define TAME_F  100000.0f
#define TAME2_F 1.0e10f
#define NTHR    128
#define BFIX    4096
#define TFIX    8760
#define CHUNK   24                    // 8760 = 24 * 365
#define NCHUNK  (TFIX / CHUNK)        // 365
#define ROWB    (NTHR * 12)           // 1536 B per time row per cluster
#define BUFB    (CHUNK * ROWB)        // 36864 B per buffer
#define SM_HDR  64                    // mbarrier header
#define GROWF   (BFIX * 3)            // out floats per time row

__device__ __forceinline__ float frsq(float x) {
    float r;
    asm("rsqrt.approx.f32 %0, %1;" : "=f"(r) : "f"(x));
    return r;
}
__device__ __forceinline__ uint32_t smem_u32(const void* p) {
    uint32_t a;
    asm("{ .reg .u64 t; cvta.to.shared.u64 t, %1; cvt.u32.u64 %0, t; }"
        : "=r"(a) : "l"(p));
    return a;
}
__device__ __forceinline__ uint32_t ctarank() {
    uint32_t r;
    asm("mov.u32 %0, %%cluster_ctarank;" : "=r"(r));
    return r;
}
__device__ __forceinline__ uint32_t mapa_u32(uint32_t addr, uint32_t rank) {
    uint32_t d;
    asm("mapa.shared::cluster.u32 %0, %1, %2;" : "=r"(d) : "r"(addr), "r"(rank));
    return d;
}
__device__ __forceinline__ void sts_cluster(uint32_t a, float v) {
    asm volatile("st.shared::cluster.f32 [%0], %1;" :: "r"(a), "f"(v) : "memory");
}
__device__ __forceinline__ void mbar_init(uint32_t a, uint32_t n) {
    asm volatile("mbarrier.init.shared.b64 [%0], %1;" :: "r"(a), "r"(n) : "memory");
}
__device__ __forceinline__ void mbar_arrive_remote(uint32_t a) {
    asm volatile("mbarrier.arrive.release.cluster.shared::cluster.b64 _, [%0];"
                 :: "r"(a) : "memory");
}
__device__ __forceinline__ void mbar_wait(uint32_t a, uint32_t par) {
    asm volatile(
        "{\n\t.reg .pred P;\n\t"
        "WL_%=:\n\t"
        "mbarrier.try_wait.parity.acquire.cluster.shared::cta.b64 P, [%0], %1, 0x989680;\n\t"
        "@P bra.uni WD_%=;\n\t"
        "bra.uni WL_%=;\n\t"
        "WD_%=:\n\t}"
        :: "r"(a), "r"(par) : "memory");
}
#define CLUSTER_SYNC() do {                                            \
    asm volatile("barrier.cluster.arrive.aligned;" ::: "memory");      \
    asm volatile("barrier.cluster.wait.aligned;" ::: "memory");        \
} while (0)

// Cluster (2,1,1): rank 0 = compute CTA (4 warps, one per SMSP, each thread
// one system); rank 1 = store CTA on a DIFFERENT SM. Compute threads push
// each step's 12 B into rank 1's smem ring via st.shared::cluster (issue-only,
// off-chain); rank 1 drains 24-row chunks to gmem with STG.cs. This removes
// the 15 cyc/step of STG issue cost from the compute warp's dispatch budget
// without stealing any of its SMSP slots (the R2/R3/R7 failure mode).
// smem layout (both ranks, same allocation):
//   [0..16)   full[2] mbarriers (used in rank1's smem)
//   [16..32)  empty[2] mbarriers (used in rank0's smem)
//   [64..)    rank0: ed rows (float4 x 8762) ; rank1: ring buffers (2 x 36864)
__global__ void __launch_bounds__(NTHR, 1) __cluster_dims__(2, 1, 1)
tithte_kernel(const float* __restrict__ state0,
              const float* __restrict__ params,
              const float* __restrict__ ed,
              const int*   __restrict__ dtp,
              float*       __restrict__ out)
{
    extern __shared__ char smem[];
    const uint32_t smem_base = smem_u32(smem);
    const int tid = threadIdx.x;
    const uint32_t rank = ctarank();

    if (rank == 0) {
        // stage external data rows {T_out, heat, solar, 0}, zero-pad 2 rows
        float4* sm4 = (float4*)(smem + SM_HDR);
        #pragma unroll 4
        for (int r = tid; r < TFIX + 2; r += NTHR) {
            float4 v = make_float4(0.f, 0.f, 0.f, 0.f);
            if (r < TFIX) { v.x = ed[3*r]; v.y = ed[3*r+1]; v.z = ed[3*r+2]; }
            sm4[r] = v;
        }
        if (tid == 0) {                       // my barriers: empty[2]
            mbar_init(smem_base + 16, NTHR);
            mbar_init(smem_base + 24, NTHR);
        }
    } else {
        if (tid == 0) {                       // my barriers: full[2]
            mbar_init(smem_base + 0, NTHR);
            mbar_init(smem_base + 8, NTHR);
        }
    }
    __syncthreads();
    CLUSTER_SYNC();                           // barriers + ed visible cluster-wide

    if (rank == 0) {
        // ================= compute CTA =================
        const float4* sm4 = (const float4*)(smem + SM_HDR);
        const int b = (blockIdx.x >> 1) * NTHR + tid;

        const float dtf = (float)dtp[0];
        const float C1 = params[b*6+0], R1 = params[b*6+1];
        const float C2 = params[b*6+2], R2 = params[b*6+3];
        const float C3 = params[b*6+4], R3 = params[b*6+5];

        const float a1 = dtf / C1, a2 = dtf / C2, a3 = dtf / C3;
        const float iR1 = 1.0f / R1, iR2 = 1.0f / R2, iR3 = 1.0f / R3;

        const float m12 = a1 * iR2, m13 = a1 * iR1, m11 = -(m12 + m13);
        const float m21 = a2 * iR2, m22 = -m21;
        const float m31 = a3 * iR1, k33 = a3 * iR3, m33 = -(m31 + k33);

        float s1 = state0[b*3+0], s2 = state0[b*3+1], s3 = state0[b*3+2];

        // prologue: x(0), h(0), tx(0), r(0) from row 0
        float4 row0 = sm4[0];
        float c1 = a1  * row0.z;
        float c2 = a2  * row0.y;
        float c3 = k33 * row0.x;
        float u1 = fmaf(m12, s2, fmaf(m13, s3, c1));
        float u2 = fmaf(m22, s2, c2);
        float u3 = fmaf(m33, s3, c3);
        float x1 = fmaf(m11, s1, u1);
        float x2 = fmaf(m21, s1, u2);
        float x3 = fmaf(m31, s1, u3);
        float h3 = fmaf(x3, x3, TAME2_F);
        float r3 = frsq(h3);
        float tx3 = x3 * TAME_F;
        float h2 = fmaf(x2, x2, TAME2_F);
        float r2 = frsq(h2);
        float tx2 = x2 * TAME_F;
        float h1 = fmaf(x1, x1, TAME2_F);
        float r1 = frsq(h1);
        float tx1 = x1 * TAME_F;

        float4 nr = sm4[1];                   // prefetched row 1

        const uint32_t buf_remote  = mapa_u32(smem_base + SM_HDR, 1);
        const uint32_t full_remote = mapa_u32(smem_base, 1);
        const float4* tp = sm4;               // advances 24 rows per chunk

        // one step: consume r, update s, push s to remote ring, build next x/h/r
#define STEP(J)                                                          \
        {                                                                \
            s3 = fmaf(tx3, r3, s3);                                      \
            s2 = fmaf(tx2, r2, s2);                                      \
            s1 = fmaf(tx1, r1, s1);                                      \
            uint32_t _a = sb + (J) * ROWB;                               \
            sts_cluster(_a + 0, s1);                                     \
            sts_cluster(_a + 4, s2);                                     \
            sts_cluster(_a + 8, s3);                                     \
            c1 = a1  * nr.z;                                             \
            c2 = a2  * nr.y;                                             \
            c3 = k33 * nr.x;                                             \
            nr = tp[(J) + 2];                                            \
            u1 = fmaf(m12, s2, fmaf(m13, s3, c1));                       \
            u2 = fmaf(m22, s2, c2);                                      \
            u3 = fmaf(m33, s3, c3);                                      \
            x1 = fmaf(m11, s1, u1);                                      \
            x2 = fmaf(m21, s1, u2);                                      \
            x3 = fmaf(m31, s1, u3);                                      \
            h3 = fmaf(x3, x3, TAME2_F);                                  \
            r3 = frsq(h3);                                               \
            tx3 = x3 * TAME_F;                                           \
            h2 = fmaf(x2, x2, TAME2_F);                                  \
            r2 = frsq(h2);                                               \
            tx2 = x2 * TAME_F;                                           \
            h1 = fmaf(x1, x1, TAME2_F);                                  \
            r1 = frsq(h1);                                               \
            tx1 = x1 * TAME_F;                                           \
        }

        #pragma unroll 1
        for (int chunk = 0; chunk < NCHUNK; ++chunk) {
            const int stage = chunk & 1;
            const int ph = (chunk >> 1) & 1;
            mbar_wait(smem_base + 16 + stage * 8, ph ^ 1);   // buffer free?

            uint32_t sb = buf_remote + stage * BUFB + tid * 12;
            #pragma unroll 1
            for (int g = 0; g < 3; ++g) {                    // 3 x 8 = 24 steps
                STEP(0) STEP(1) STEP(2) STEP(3)
                STEP(4) STEP(5) STEP(6) STEP(7)
                tp += 8;
                sb += 8 * ROWB;
            }
            mbar_arrive_remote(full_remote + stage * 8);     // chunk ready
        }
#undef STEP
    } else {
        // ================= store CTA =================
        const int sys = (blockIdx.x >> 1) * NTHR + tid;
        float* gp = out + (size_t)sys * 3;
        const float* bufl = (const float*)(smem + SM_HDR);
        const uint32_t empty_remote = mapa_u32(smem_base + 16, 0);

        #pragma unroll 1
        for (int chunk = 0; chunk < NCHUNK; ++chunk) {
            const int stage = chunk & 1;
            const int ph = (chunk >> 1) & 1;
            mbar_wait(smem_base + stage * 8, ph);            // chunk ready?

            const float* bp = bufl + stage * (BUFB / 4) + tid * 3;
            #pragma unroll 6
            for (int r = 0; r < CHUNK; ++r) {
                const float v0 = bp[r * (ROWB/4) + 0];
                const float v1 = bp[r * (ROWB/4) + 1];
                const float v2 = bp[r * (ROWB/4) + 2];
                __stcs(gp + (size_t)r * GROWF + 0, v0);
                __stcs(gp + (size_t)r * GROWF + 1, v1);
                __stcs(gp + (size_t)r * GROWF + 2, v2);
            }
            gp += (size_t)CHUNK * GROWF;
            mbar_arrive_remote(empty_remote + stage * 8);    // buffer free
        }
    }

    CLUSTER_SYNC();                           // no early CTA exit
}

extern "C" void kernel_launch(void* const* d_in, const int* in_sizes, int n_in,
                              void* d_out, int out_size) {
    const float* state0 = (const float*)d_in[0];
    const float* params = (const float*)d_in[1];
    const float* ed     = (const float*)d_in[2];
    const int*   dtp    = (const int*)d_in[3];
    float* out = (float*)d_out;

    const int blocks = 2 * (BFIX / NTHR);     // 64 blocks = 32 clusters of 2
    const size_t smem = SM_HDR + (size_t)(TFIX + 2) * sizeof(float4); // 140256 B

    cudaFuncSetAttribute(tithte_kernel,
                         cudaFuncAttributeMaxDynamicSharedMemorySize, (int)smem);
    tithte_kernel<<<blocks, NTHR, smem>>>(state0, params, ed, dtp, out);
}

// round 14
// speedup vs baseline: 5.8505x; 5.8505x over previous
#include <cuda_runtime.h>
#include <cstdint>
#include <cstddef>

#define TAME_F  100000.0f
#define TAME2_F 1.0e10f
#define NTHR    128
#define BFIX    4096
#define TFIX    8760
#define GROW3   (BFIX * 3)          // out floats per time row

__device__ __forceinline__ float frsq(float x) {
    float r;
    asm("rsqrt.approx.f32 %0, %1;" : "=f"(r) : "f"(x));
    return r;
}

// k=1, 32 blocks x 128 threads: 128 warps on 128 distinct SMSPs (R7/R11/R13:
// every sharing or offload scheme regressed). Body is dispatch-occupancy
// bound at ~68 cyc/step vs a ~62-cyc ledger; this round deepens the unroll to
// 12 (one pointer bump per 12 steps for BOTH the output and the smem row
// stream, immediate offsets everywhere) to shave loop/address overhead and
// widen the scheduling window.
__global__ void __launch_bounds__(NTHR, 1)
tithte_kernel(const float* __restrict__ state0,
              const float* __restrict__ params,
              const float* __restrict__ ed,
              const int*   __restrict__ dtp,
              float*       __restrict__ out)
{
    extern __shared__ float4 sm4[];   // [0..TFIX+1] rows {T_out, heat, solar, 0}

    const int tid = threadIdx.x;

    #pragma unroll 4
    for (int r = tid; r < TFIX + 2; r += NTHR) {
        float4 v = make_float4(0.f, 0.f, 0.f, 0.f);
        if (r < TFIX) { v.x = ed[3*r]; v.y = ed[3*r+1]; v.z = ed[3*r+2]; }
        sm4[r] = v;
    }
    __syncthreads();

    const int b = blockIdx.x * NTHR + tid;

    const float dtf = (float)dtp[0];
    const float C1 = params[b*6+0], R1 = params[b*6+1];
    const float C2 = params[b*6+2], R2 = params[b*6+3];
    const float C3 = params[b*6+4], R3 = params[b*6+5];

    const float a1 = dtf / C1, a2 = dtf / C2, a3 = dtf / C3;
    const float iR1 = 1.0f / R1, iR2 = 1.0f / R2, iR3 = 1.0f / R3;

    const float m12 = a1 * iR2, m13 = a1 * iR1, m11 = -(m12 + m13);
    const float m21 = a2 * iR2, m22 = -m21;
    const float m31 = a3 * iR1, k33 = a3 * iR3, m33 = -(m31 + k33);

    float s1 = state0[b*3+0], s2 = state0[b*3+1], s3 = state0[b*3+2];

    // ---- prologue: step-0 x, h, tx, r from row 0 ----
    float4 row0 = sm4[0];
    float c1 = a1  * row0.z;
    float c2 = a2  * row0.y;
    float c3 = k33 * row0.x;
    float u1 = fmaf(m12, s2, fmaf(m13, s3, c1));
    float u2 = fmaf(m22, s2, c2);
    float u3 = fmaf(m33, s3, c3);
    float x1 = fmaf(m11, s1, u1);
    float x2 = fmaf(m21, s1, u2);
    float x3 = fmaf(m31, s1, u3);
    float h3 = fmaf(x3, x3, TAME2_F);
    float r3 = frsq(h3);
    float tx3 = x3 * TAME_F;
    float h2 = fmaf(x2, x2, TAME2_F);
    float r2 = frsq(h2);
    float tx2 = x2 * TAME_F;
    float h1 = fmaf(x1, x1, TAME2_F);
    float r1 = frsq(h1);
    float tx1 = x1 * TAME_F;

    const float4* tp = sm4 + 1;   // row (t+1) stream, bumped once per 12 steps
    float4 nr = tp[0];            // prefetched row 1

    float* op = out + (size_t)b * 3;

    // ---- peeled t = 0 (no previous row to store) ----
    {
        c1 = a1  * nr.z;
        c2 = a2  * nr.y;
        c3 = k33 * nr.x;
        nr = tp[1];
        s3 = fmaf(tx3, r3, s3);
        s2 = fmaf(tx2, r2, s2);
        s1 = fmaf(tx1, r1, s1);
        u1 = fmaf(m12, s2, fmaf(m13, s3, c1));
        u2 = fmaf(m22, s2, c2);
        u3 = fmaf(m33, s3, c3);
        x1 = fmaf(m11, s1, u1);
        x2 = fmaf(m21, s1, u2);
        x3 = fmaf(m31, s1, u3);
        h3 = fmaf(x3, x3, TAME2_F);
        r3 = frsq(h3);
        tx3 = x3 * TAME_F;
        h2 = fmaf(x2, x2, TAME2_F);
        r2 = frsq(h2);
        tx2 = x2 * TAME_F;
        h1 = fmaf(x1, x1, TAME2_F);
        r1 = frsq(h1);
        tx1 = x1 * TAME_F;
    }
    tp += 1;   // tp now points at row (t+1) for t = 1

    // one step: store s(t-1) at immediate offset, advance recurrence.
    // J indexes both the output row and the prefetched ed row.
#define STEP(J)                                                              \
    {                                                                        \
        __stcs(op + (J)*GROW3 + 0, s1);                                      \
        __stcs(op + (J)*GROW3 + 1, s2);                                      \
        __stcs(op + (J)*GROW3 + 2, s3);                                      \
        c1 = a1  * nr.z;                                                     \
        c2 = a2  * nr.y;                                                     \
        c3 = k33 * nr.x;                                                     \
        nr = tp[(J) + 1];                                                    \
        s3 = fmaf(tx3, r3, s3);                                              \
        s2 = fmaf(tx2, r2, s2);                                              \
        s1 = fmaf(tx1, r1, s1);                                              \
        u1 = fmaf(m12, s2, fmaf(m13, s3, c1));                               \
        u2 = fmaf(m22, s2, c2);                                              \
        u3 = fmaf(m33, s3, c3);                                              \
        x1 = fmaf(m11, s1, u1);                                              \
        x2 = fmaf(m21, s1, u2);                                              \
        x3 = fmaf(m31, s1, u3);                                              \
        h3 = fmaf(x3, x3, TAME2_F);                                          \
        r3 = frsq(h3);                                                       \
        tx3 = x3 * TAME_F;                                                   \
        h2 = fmaf(x2, x2, TAME2_F);                                          \
        r2 = frsq(h2);                                                       \
        tx2 = x2 * TAME_F;                                                   \
        h1 = fmaf(x1, x1, TAME2_F);                                          \
        r1 = frsq(h1);                                                       \
        tx1 = x1 * TAME_F;                                                   \
    }

    // main: t = 1 .. 8748 in 729 chunks of 12
    #pragma unroll 1
    for (int blk = 0; blk < 729; ++blk) {
        STEP(0)  STEP(1)  STEP(2)  STEP(3)
        STEP(4)  STEP(5)  STEP(6)  STEP(7)
        STEP(8)  STEP(9)  STEP(10) STEP(11)
        op += 12 * GROW3;
        tp += 12;
    }
    // tail: t = 8749 .. 8759 (11 steps; smem rows zero-padded past TFIX)
    STEP(0)  STEP(1)  STEP(2)  STEP(3)
    STEP(4)  STEP(5)  STEP(6)  STEP(7)
    STEP(8)  STEP(9)  STEP(10)
    op += 11 * GROW3;

    // final row T-1
    __stcs(op + 0, s1);
    __stcs(op + 1, s2);
    __stcs(op + 2, s3);
#undef STEP
}

extern "C" void kernel_launch(void* const* d_in, const int* in_sizes, int n_in,
                              void* d_out, int out_size) {
    const float* state0 = (const float*)d_in[0];
    const float* params = (const float*)d_in[1];
    const float* ed     = (const float*)d_in[2];
    const int*   dtp    = (const int*)d_in[3];
    float* out = (float*)d_out;

    const int blocks = BFIX / NTHR;   // 32 -> 1 warp per SMSP chip-wide
    const size_t smem = (size_t)(TFIX + 2) * sizeof(float4);

    cudaFuncSetAttribute(tithte_kernel,
                         cudaFuncAttributeMaxDynamicSharedMemorySize, (int)smem);
    tithte_kernel<<<blocks, NTHR, smem>>>(state0, params, ed, dtp, out);
}